// round 1
// baseline (speedup 1.0000x reference)
#include <cuda_runtime.h>

// ---------------- problem constants ----------------
#define BATCH 8192
#define NNODE 30
#define FEAT  256
#define MROWS (BATCH * NNODE)   // 245760

// ---------------- scratch (device globals; no allocation) ----------------
__device__ float g_adj[(size_t)BATCH * NNODE * NNODE];   // 29.5 MB
__device__ float g_u[(size_t)BATCH * NNODE * FEAT];      // 251.7 MB
__device__ float g_h[(size_t)BATCH * NNODE * FEAT];      // 251.7 MB

// =====================================================================
// Kernel 1/3: C[M,256] = A[M,256] @ B[256,256]
// 128x128 CTA tile, K-step 16, double-buffered smem, 8x8 per thread.
// M = 245760 (divisible by 128), grid = (1920, 2).
// =====================================================================
__global__ __launch_bounds__(256, 2)
void sgemm256(const float* __restrict__ A, const float* __restrict__ Bw,
              float* __restrict__ C) {
    __shared__ __align__(16) float As[2][16][132];  // padded: conflict-free transpose store
    __shared__ __align__(16) float Bs[2][16][128];

    const int tid = threadIdx.x;
    const int bm = blockIdx.x;
    const int bn = blockIdx.y;

    // global-load assignments
    const int aRow = tid >> 2;           // 0..63
    const int aCol = (tid & 3) << 2;     // 0,4,8,12
    const int bRow = tid >> 5;           // 0..7
    const int bCol = (tid & 31) << 2;    // 0..124

    const float* Ap = A + (size_t)bm * 128 * 256;
    const float* Bp = Bw + bn * 128;

    float4 a0 = *(const float4*)(Ap + (size_t)aRow * 256 + aCol);
    float4 a1 = *(const float4*)(Ap + (size_t)(aRow + 64) * 256 + aCol);
    float4 b0 = *(const float4*)(Bp + (size_t)bRow * 256 + bCol);
    float4 b1 = *(const float4*)(Bp + (size_t)(bRow + 8) * 256 + bCol);

    const int tx = (tid & 15) << 3;      // output col offset within tile
    const int ty = (tid >> 4) << 3;      // output row offset within tile

    float acc[8][8] = {};

    #pragma unroll 1
    for (int kt = 0; kt < 16; ++kt) {
        const int buf = kt & 1;
        // store prefetched tile (A transposed to k-major)
        As[buf][aCol + 0][aRow] = a0.x;
        As[buf][aCol + 1][aRow] = a0.y;
        As[buf][aCol + 2][aRow] = a0.z;
        As[buf][aCol + 3][aRow] = a0.w;
        As[buf][aCol + 0][aRow + 64] = a1.x;
        As[buf][aCol + 1][aRow + 64] = a1.y;
        As[buf][aCol + 2][aRow + 64] = a1.z;
        As[buf][aCol + 3][aRow + 64] = a1.w;
        *(float4*)&Bs[buf][bRow][bCol]     = b0;
        *(float4*)&Bs[buf][bRow + 8][bCol] = b1;
        __syncthreads();

        if (kt < 15) {
            const float* An = Ap + (kt + 1) * 16;
            a0 = *(const float4*)(An + (size_t)aRow * 256 + aCol);
            a1 = *(const float4*)(An + (size_t)(aRow + 64) * 256 + aCol);
            const float* Bn = Bp + (size_t)(kt + 1) * 16 * 256;
            b0 = *(const float4*)(Bn + (size_t)bRow * 256 + bCol);
            b1 = *(const float4*)(Bn + (size_t)(bRow + 8) * 256 + bCol);
        }

        #pragma unroll
        for (int k = 0; k < 16; ++k) {
            float af[8], bf[8];
            *(float4*)&af[0] = *(const float4*)&As[buf][k][ty];
            *(float4*)&af[4] = *(const float4*)&As[buf][k][ty + 4];
            *(float4*)&bf[0] = *(const float4*)&Bs[buf][k][tx];
            *(float4*)&bf[4] = *(const float4*)&Bs[buf][k][tx + 4];
            #pragma unroll
            for (int i = 0; i < 8; ++i)
                #pragma unroll
                for (int j = 0; j < 8; ++j)
                    acc[i][j] = fmaf(af[i], bf[j], acc[i][j]);
        }
    }

    float* Cp = C + (size_t)(bm * 128 + ty) * 256 + bn * 128 + tx;
    #pragma unroll
    for (int i = 0; i < 8; ++i) {
        float4 v0 = make_float4(acc[i][0], acc[i][1], acc[i][2], acc[i][3]);
        float4 v1 = make_float4(acc[i][4], acc[i][5], acc[i][6], acc[i][7]);
        *(float4*)(Cp + (size_t)i * 256)     = v0;
        *(float4*)(Cp + (size_t)i * 256 + 4) = v1;
    }
}

// =====================================================================
// Kernel 2: per-batch  h1 = relu(adj @ u1 + b1), adj = mean(graph, bands)
// 4 batches per CTA, 64 threads per batch, each thread owns a float4 of
// columns; u rows preloaded into 120 registers; adj broadcast from smem.
// =====================================================================
__global__ __launch_bounds__(256)
void gcn1(const float* __restrict__ graph, const float* __restrict__ u,
          const float* __restrict__ bias1, float* __restrict__ adj,
          float* __restrict__ h) {
    __shared__ float adj_s[4][900];
    const int tid = threadIdx.x;
    const int g = tid >> 6;
    const int lane = tid & 63;
    const size_t b = (size_t)blockIdx.x * 4 + g;

    // adj = 0.2 * sum over 5 bands
    const float* gp = graph + b * 4500;
    float* ao = adj + b * 900;
    for (int e = lane; e < 900; e += 64) {
        float s = 0.2f * (gp[e] + gp[e + 900] + gp[e + 1800] + gp[e + 2700] + gp[e + 3600]);
        adj_s[g][e] = s;
        ao[e] = s;
    }

    const int j = lane << 2;
    const float* up = u + b * 7680 + j;
    float4 ur[30];
    #pragma unroll
    for (int k = 0; k < 30; ++k) ur[k] = *(const float4*)(up + (size_t)k * 256);
    const float4 bb = *(const float4*)(bias1 + j);
    __syncthreads();

    float* hp = h + b * 7680 + j;
    #pragma unroll 1
    for (int i = 0; i < 30; ++i) {
        float4 acc = make_float4(0.f, 0.f, 0.f, 0.f);
        const float* ar = &adj_s[g][i * 30];
        #pragma unroll
        for (int k = 0; k < 30; ++k) {
            const float a = ar[k];
            acc.x = fmaf(a, ur[k].x, acc.x);
            acc.y = fmaf(a, ur[k].y, acc.y);
            acc.z = fmaf(a, ur[k].z, acc.z);
            acc.w = fmaf(a, ur[k].w, acc.w);
        }
        float4 o;
        o.x = fmaxf(acc.x + bb.x, 0.f);
        o.y = fmaxf(acc.y + bb.y, 0.f);
        o.z = fmaxf(acc.z + bb.z, 0.f);
        o.w = fmaxf(acc.w + bb.w, 0.f);
        *(float4*)(hp + (size_t)i * 256) = o;
    }
}

// =====================================================================
// Kernel 4: per-batch  g2 = adj @ u2 + b2 ; h2 = relu(g2);
// xl = relu(h2 @ w_lin + b_lin); out = xl @ W_head^T + b_head
// Fully fused: writes d_out [B,9] directly.
// =====================================================================
__global__ __launch_bounds__(256)
void gcn2(const float* __restrict__ adj, const float* __restrict__ u,
          const float* __restrict__ bias2, const float* __restrict__ wlin,
          const float* __restrict__ blin, const float* __restrict__ Whead,
          const float* __restrict__ bhead, float* __restrict__ out) {
    __shared__ float adj_s[4][900];
    __shared__ float part_s[4][30][2];
    __shared__ float xl_s[4][30];

    const int tid = threadIdx.x;
    const int g = tid >> 6;
    const int lane = tid & 63;
    const int w = lane >> 5;          // warp within group (0/1)
    const size_t b = (size_t)blockIdx.x * 4 + g;

    const float* ap = adj + b * 900;
    for (int e = lane; e < 900; e += 64) adj_s[g][e] = ap[e];

    const int j = lane << 2;
    const float* up = u + b * 7680 + j;
    float4 ur[30];
    #pragma unroll
    for (int k = 0; k < 30; ++k) ur[k] = *(const float4*)(up + (size_t)k * 256);
    const float4 bb = *(const float4*)(bias2 + j);
    const float4 wl = *(const float4*)(wlin + j);
    __syncthreads();

    #pragma unroll 1
    for (int i = 0; i < 30; ++i) {
        float4 acc = make_float4(0.f, 0.f, 0.f, 0.f);
        const float* ar = &adj_s[g][i * 30];
        #pragma unroll
        for (int k = 0; k < 30; ++k) {
            const float a = ar[k];
            acc.x = fmaf(a, ur[k].x, acc.x);
            acc.y = fmaf(a, ur[k].y, acc.y);
            acc.z = fmaf(a, ur[k].z, acc.z);
            acc.w = fmaf(a, ur[k].w, acc.w);
        }
        float p = fmaxf(acc.x + bb.x, 0.f) * wl.x
                + fmaxf(acc.y + bb.y, 0.f) * wl.y
                + fmaxf(acc.z + bb.z, 0.f) * wl.z
                + fmaxf(acc.w + bb.w, 0.f) * wl.w;
        #pragma unroll
        for (int o = 16; o > 0; o >>= 1) p += __shfl_down_sync(0xffffffffu, p, o);
        if ((lane & 31) == 0) part_s[g][i][w] = p;
    }
    __syncthreads();

    if (lane < 30) {
        xl_s[g][lane] = fmaxf(part_s[g][lane][0] + part_s[g][lane][1] + blin[0], 0.f);
    }
    __syncthreads();

    if (lane < 9) {
        float s = bhead[lane];
        #pragma unroll
        for (int i = 0; i < 30; ++i) s = fmaf(xl_s[g][i], Whead[lane * 30 + i], s);
        out[b * 9 + lane] = s;
    }
}

// =====================================================================
// Launch: u1 = real@W1 ; h1 = relu(adj@u1+b1) ; u2 = h1@W2 ;
//         out = head(relu(lin(relu(adj@u2+b2))))
// (associativity: (adj@X)@W == adj@(X@W) — exact in real arithmetic,
//  fp32 rounding noise << 1e-3 threshold)
// =====================================================================
extern "C" void kernel_launch(void* const* d_in, const int* in_sizes, int n_in,
                              void* d_out, int out_size) {
    const float* real  = (const float*)d_in[0];
    // d_in[1] = imag (unused by the reference forward)
    const float* graph = (const float*)d_in[2];
    const float* W1    = (const float*)d_in[3];
    const float* b1    = (const float*)d_in[4];
    const float* W2    = (const float*)d_in[5];
    const float* b2    = (const float*)d_in[6];
    const float* wlin  = (const float*)d_in[7];
    const float* blin  = (const float*)d_in[8];
    const float* Whead = (const float*)d_in[9];
    const float* bhead = (const float*)d_in[10];
    float* out = (float*)d_out;

    float *adj_p, *u_p, *h_p;
    cudaGetSymbolAddress((void**)&adj_p, g_adj);
    cudaGetSymbolAddress((void**)&u_p,   g_u);
    cudaGetSymbolAddress((void**)&h_p,   g_h);

    const dim3 gemm_grid(MROWS / 128, 2);
    const int  gcn_grid = BATCH / 4;

    // u1 = real @ W1
    sgemm256<<<gemm_grid, 256>>>(real, W1, u_p);
    // adj = mean(graph); h1 = relu(adj @ u1 + b1)
    gcn1<<<gcn_grid, 256>>>(graph, u_p, b1, adj_p, h_p);
    // u2 = h1 @ W2
    sgemm256<<<gemm_grid, 256>>>(h_p, W2, u_p);
    // fused layer2 + lin + head -> out[B,9]
    gcn2<<<gcn_grid, 256>>>(adj_p, u_p, b2, wlin, blin, Whead, bhead, out);
}

// round 3
// speedup vs baseline: 1.9887x; 1.9887x over previous
#include <cuda_runtime.h>
#include <cuda_bf16.h>
#include <cstdint>

// ---------------- problem constants ----------------
#define BATCH 8192
#define NNODE 30
#define FEAT  256
#define MROWS (BATCH * NNODE)   // 245760

// ---------------- scratch (device globals; no allocation) ----------------
__device__ float          g_adj[(size_t)BATCH * NNODE * NNODE];   // 29.5 MB
__device__ float          g_h  [(size_t)MROWS * FEAT];            // 251.7 MB
__device__ __nv_bfloat16  g_ah [(size_t)MROWS * FEAT];            // 125.8 MB
__device__ __nv_bfloat16  g_al [(size_t)MROWS * FEAT];            // 125.8 MB
__device__ float          g_part[(size_t)2 * MROWS];              // 2 MB
__device__ __nv_bfloat16  g_w1h[FEAT * FEAT], g_w1l[FEAT * FEAT];
__device__ __nv_bfloat16  g_w2h[FEAT * FEAT], g_w2l[FEAT * FEAT];

// ==================== helpers ====================
__device__ __forceinline__ uint32_t smem_to_u32(const void* p) {
    uint32_t a;
    asm("{ .reg .u64 t; cvta.to.shared.u64 t, %1; cvt.u32.u64 %0, t; }" : "=r"(a) : "l"(p));
    return a;
}
__device__ __forceinline__ void cpasync16(uint32_t saddr, const void* g) {
    asm volatile("cp.async.cg.shared.global [%0], [%1], 16;" :: "r"(saddr), "l"(g));
}
__device__ __forceinline__ void ldsm4(uint32_t* r, uint32_t addr) {
    asm volatile("ldmatrix.sync.aligned.m8n8.x4.shared.b16 {%0,%1,%2,%3}, [%4];"
        : "=r"(r[0]), "=r"(r[1]), "=r"(r[2]), "=r"(r[3]) : "r"(addr));
}
__device__ __forceinline__ void mma_bf16(float* d, const uint32_t* a, uint32_t b0, uint32_t b1) {
    asm volatile(
        "mma.sync.aligned.m16n8k16.row.col.f32.bf16.bf16.f32 "
        "{%0,%1,%2,%3}, {%4,%5,%6,%7}, {%8,%9}, {%0,%1,%2,%3};"
        : "+f"(d[0]), "+f"(d[1]), "+f"(d[2]), "+f"(d[3])
        : "r"(a[0]), "r"(a[1]), "r"(a[2]), "r"(a[3]), "r"(b0), "r"(b1));
}
// ---- packed f32x2 math ----
__device__ __forceinline__ unsigned long long pk2(float x, float y) {
    unsigned long long r;
    asm("mov.b64 %0, {%1, %2};" : "=l"(r) : "f"(x), "f"(y));
    return r;
}
__device__ __forceinline__ void upk2(unsigned long long v, float& x, float& y) {
    asm("mov.b64 {%0, %1}, %2;" : "=f"(x), "=f"(y) : "l"(v));
}
__device__ __forceinline__ unsigned long long fma2(unsigned long long a,
                                                   unsigned long long b,
                                                   unsigned long long c) {
    unsigned long long d;
    asm("fma.rn.f32x2 %0, %1, %2, %3;" : "=l"(d) : "l"(a), "l"(b), "l"(c));
    return d;
}

// =====================================================================
// prep_w: transpose W1/W2 to [N,K] K-major and split into bf16 hi/lo
// =====================================================================
__global__ void prep_w(const float* __restrict__ W1, const float* __restrict__ W2,
                       __nv_bfloat16* __restrict__ w1h, __nv_bfloat16* __restrict__ w1l,
                       __nv_bfloat16* __restrict__ w2h, __nv_bfloat16* __restrict__ w2l) {
    const int n = blockIdx.x, k = threadIdx.x;
    float v1 = W1[k * 256 + n];
    __nv_bfloat16 h1 = __float2bfloat16_rn(v1);
    w1h[n * 256 + k] = h1;
    w1l[n * 256 + k] = __float2bfloat16_rn(v1 - __bfloat162float(h1));
    float v2 = W2[k * 256 + n];
    __nv_bfloat16 h2 = __float2bfloat16_rn(v2);
    w2h[n * 256 + k] = h2;
    w2l[n * 256 + k] = __float2bfloat16_rn(v2 - __bfloat162float(h2));
}

// =====================================================================
// k_prep: adj = mean(graph, bands); y1 = adj @ real -> bf16 hi/lo
// =====================================================================
__global__ __launch_bounds__(128)
void k_prep(const float* __restrict__ graph, const float* __restrict__ x,
            float* __restrict__ adj_out,
            __nv_bfloat16* __restrict__ ah, __nv_bfloat16* __restrict__ al) {
    __shared__ float adj_s[900];
    const int tid = threadIdx.x;
    const size_t b = blockIdx.x;

    const float* gp = graph + b * 4500;
    float* ao = adj_out + b * 900;
    for (int e = tid; e < 900; e += 128) {
        float s = 0.2f * (gp[e] + gp[e + 900] + gp[e + 1800] + gp[e + 2700] + gp[e + 3600]);
        adj_s[e] = s;
        ao[e] = s;
    }

    const int j = tid * 2;
    const float* xp = x + b * 7680 + j;
    unsigned long long xr[30];
    #pragma unroll
    for (int k = 0; k < 30; ++k) {
        float2 v = *(const float2*)(xp + (size_t)k * 256);
        xr[k] = pk2(v.x, v.y);
    }
    __syncthreads();

    #pragma unroll 1
    for (int i = 0; i < 30; ++i) {
        unsigned long long acc = 0ULL;
        const float* ar = adj_s + i * 30;
        #pragma unroll
        for (int k = 0; k < 30; ++k) {
            float a = ar[k];
            acc = fma2(pk2(a, a), xr[k], acc);
        }
        float y0, y1;
        upk2(acc, y0, y1);
        __nv_bfloat16 h0 = __float2bfloat16_rn(y0);
        __nv_bfloat16 h1 = __float2bfloat16_rn(y1);
        __nv_bfloat162 hv, lv;
        hv.x = h0; hv.y = h1;
        lv.x = __float2bfloat16_rn(y0 - __bfloat162float(h0));
        lv.y = __float2bfloat16_rn(y1 - __bfloat162float(h1));
        size_t ro = (b * 30 + i) * 256 + j;
        *(__nv_bfloat162*)(ah + ro) = hv;
        *(__nv_bfloat162*)(al + ro) = lv;
    }
}

// =====================================================================
// k_g2: g2 = adj @ h1 -> bf16 hi/lo
// =====================================================================
__global__ __launch_bounds__(128)
void k_g2(const float* __restrict__ adj, const float* __restrict__ h,
          __nv_bfloat16* __restrict__ ah, __nv_bfloat16* __restrict__ al) {
    __shared__ float adj_s[900];
    const int tid = threadIdx.x;
    const size_t b = blockIdx.x;

    const float* ap = adj + b * 900;
    for (int e = tid; e < 900; e += 128) adj_s[e] = ap[e];

    const int j = tid * 2;
    const float* hp = h + b * 7680 + j;
    unsigned long long xr[30];
    #pragma unroll
    for (int k = 0; k < 30; ++k) {
        float2 v = *(const float2*)(hp + (size_t)k * 256);
        xr[k] = pk2(v.x, v.y);
    }
    __syncthreads();

    #pragma unroll 1
    for (int i = 0; i < 30; ++i) {
        unsigned long long acc = 0ULL;
        const float* ar = adj_s + i * 30;
        #pragma unroll
        for (int k = 0; k < 30; ++k) {
            float a = ar[k];
            acc = fma2(pk2(a, a), xr[k], acc);
        }
        float y0, y1;
        upk2(acc, y0, y1);
        __nv_bfloat16 h0 = __float2bfloat16_rn(y0);
        __nv_bfloat16 h1 = __float2bfloat16_rn(y1);
        __nv_bfloat162 hv, lv;
        hv.x = h0; hv.y = h1;
        lv.x = __float2bfloat16_rn(y0 - __bfloat162float(h0));
        lv.y = __float2bfloat16_rn(y1 - __bfloat162float(h1));
        size_t ro = (b * 30 + i) * 256 + j;
        *(__nv_bfloat162*)(ah + ro) = hv;
        *(__nv_bfloat162*)(al + ro) = lv;
    }
}

// =====================================================================
// HMMA split-bf16 GEMM: C[128,128-tile] = A[M,256] @ Wt[N,256]^T
// 3 passes: Ah*Wh + Ah*Wl + Al*Wh, fp32 accum in registers.
// MODE 1: Out = relu(C + bias)  -> h [M,256]
// MODE 2: partial[bn*M + r] = sum_cols relu(C+bias)*wlin (half-N partial)
// smem: 2 stages x 4 arrays (Ah,Al,Wh,Wl) x 16KB, SW128 swizzle.
// =====================================================================
#define GEMM_SMEM 131072

template <int MODE>
__global__ __launch_bounds__(256, 1)
void gemm_hmma(const __nv_bfloat16* __restrict__ Ah, const __nv_bfloat16* __restrict__ Al,
               const __nv_bfloat16* __restrict__ Wh, const __nv_bfloat16* __restrict__ Wl,
               const float* __restrict__ bias, const float* __restrict__ wlin,
               float* __restrict__ Out) {
    extern __shared__ char smem[];
    const uint32_t sb = smem_to_u32(smem);
    const int tid = threadIdx.x;
    const int lane = tid & 31;
    const int wid = tid >> 5;
    const int warp_m = wid & 3;     // 4 row groups of 32
    const int warp_n = wid >> 2;    // 2 col groups of 64
    const size_t arow0 = (size_t)blockIdx.x * 128;
    const int ncol0 = blockIdx.y * 128;

    // ldmatrix lane address components
    const int matv = lane >> 3;                           // which 8x8 matrix
    const int rA0 = warp_m * 32 + (matv & 1) * 8 + (lane & 7);
    const int kAoff = (matv >> 1) * 16;                   // byte offset
    const int rB0 = warp_n * 64 + matv * 8 + (lane & 7);
    const uint32_t xorv = (uint32_t)((lane & 7) << 4);    // SW128 xor

    auto issue_stage = [&](int c) {
        const uint32_t st = sb + (uint32_t)(c & 1) * 65536u;
        const __nv_bfloat16* gA  = Ah + arow0 * 256 + c * 64;
        const __nv_bfloat16* gL  = Al + arow0 * 256 + c * 64;
        const __nv_bfloat16* gWh = Wh + (size_t)ncol0 * 256 + c * 64;
        const __nv_bfloat16* gWl = Wl + (size_t)ncol0 * 256 + c * 64;
        #pragma unroll
        for (int it = 0; it < 4; ++it) {
            int u = it * 256 + tid;
            int row = u >> 3, seg = u & 7;
            uint32_t so = (uint32_t)(row * 128 + ((seg * 16) ^ ((row & 7) * 16)));
            size_t go = (size_t)row * 256 + seg * 8;
            cpasync16(st + so,           gA + go);
            cpasync16(st + 16384u + so,  gL + go);
            cpasync16(st + 32768u + so,  gWh + go);
            cpasync16(st + 49152u + so,  gWl + go);
        }
        asm volatile("cp.async.commit_group;" ::: "memory");
    };

    float acc[2][8][4] = {};

    issue_stage(0);
    issue_stage(1);

    #pragma unroll 1
    for (int c = 0; c < 4; ++c) {
        if (c < 3) asm volatile("cp.async.wait_group 1;" ::: "memory");
        else       asm volatile("cp.async.wait_group 0;" ::: "memory");
        __syncthreads();

        const uint32_t st = sb + (uint32_t)(c & 1) * 65536u;
        #pragma unroll
        for (int ks = 0; ks < 4; ++ks) {
            uint32_t ah_f[2][4], al_f[2][4];
            #pragma unroll
            for (int mt = 0; mt < 2; ++mt) {
                uint32_t ro = (uint32_t)((rA0 + mt * 16) * 128);
                uint32_t co = (uint32_t)((ks * 32 + kAoff) ^ (int)xorv);
                ldsm4(ah_f[mt], st + ro + co);
                ldsm4(al_f[mt], st + 16384u + ro + co);
            }
            uint32_t b0h[8], b1h[8], b0l[8], b1l[8];
            #pragma unroll
            for (int jb = 0; jb < 2; ++jb) {
                uint32_t ro = (uint32_t)((rB0 + jb * 32) * 128);
                uint32_t c0 = (uint32_t)((ks * 32) ^ (int)xorv);
                uint32_t c1 = (uint32_t)((ks * 32 + 16) ^ (int)xorv);
                ldsm4(&b0h[jb * 4], st + 32768u + ro + c0);
                ldsm4(&b1h[jb * 4], st + 32768u + ro + c1);
                ldsm4(&b0l[jb * 4], st + 49152u + ro + c0);
                ldsm4(&b1l[jb * 4], st + 49152u + ro + c1);
            }
            #pragma unroll
            for (int mt = 0; mt < 2; ++mt)
                #pragma unroll
                for (int j = 0; j < 8; ++j) {
                    mma_bf16(acc[mt][j], ah_f[mt], b0h[j], b1h[j]);
                    mma_bf16(acc[mt][j], ah_f[mt], b0l[j], b1l[j]);
                    mma_bf16(acc[mt][j], al_f[mt], b0h[j], b1h[j]);
                }
        }
        __syncthreads();
        if (c + 2 < 4) issue_stage(c + 2);
    }

    // ---------------- epilogue ----------------
    const int g = lane >> 2;          // row within m16 tile
    const int cq = (lane & 3) * 2;    // col pair within n8 tile

    if (MODE == 1) {
        #pragma unroll
        for (int mt = 0; mt < 2; ++mt) {
            const size_t r0 = arow0 + warp_m * 32 + mt * 16 + g;
            #pragma unroll
            for (int j = 0; j < 8; ++j) {
                const int col = ncol0 + warp_n * 64 + j * 8 + cq;
                const float b0 = __ldg(bias + col), b1 = __ldg(bias + col + 1);
                float2 v0, v1;
                v0.x = fmaxf(acc[mt][j][0] + b0, 0.f);
                v0.y = fmaxf(acc[mt][j][1] + b1, 0.f);
                v1.x = fmaxf(acc[mt][j][2] + b0, 0.f);
                v1.y = fmaxf(acc[mt][j][3] + b1, 0.f);
                *(float2*)(Out + r0 * 256 + col)       = v0;
                *(float2*)(Out + (r0 + 8) * 256 + col) = v1;
            }
        }
    } else {
        float px[2][2] = {};
        #pragma unroll
        for (int mt = 0; mt < 2; ++mt)
            #pragma unroll
            for (int j = 0; j < 8; ++j) {
                const int col = ncol0 + warp_n * 64 + j * 8 + cq;
                const float b0 = __ldg(bias + col), b1 = __ldg(bias + col + 1);
                const float w0 = __ldg(wlin + col), w1 = __ldg(wlin + col + 1);
                px[mt][0] += fmaxf(acc[mt][j][0] + b0, 0.f) * w0
                           + fmaxf(acc[mt][j][1] + b1, 0.f) * w1;
                px[mt][1] += fmaxf(acc[mt][j][2] + b0, 0.f) * w0
                           + fmaxf(acc[mt][j][3] + b1, 0.f) * w1;
            }
        // reduce across the 4 lanes sharing a row
        #pragma unroll
        for (int mt = 0; mt < 2; ++mt)
            #pragma unroll
            for (int hh = 0; hh < 2; ++hh) {
                float v = px[mt][hh];
                v += __shfl_xor_sync(0xffffffffu, v, 1);
                v += __shfl_xor_sync(0xffffffffu, v, 2);
                px[mt][hh] = v;
            }
        float* ps = (float*)smem;
        if (warp_n == 0 && (lane & 3) == 0) {
            #pragma unroll
            for (int mt = 0; mt < 2; ++mt)
                #pragma unroll
                for (int hh = 0; hh < 2; ++hh)
                    ps[warp_m * 32 + mt * 16 + hh * 8 + g] = px[mt][hh];
        }
        __syncthreads();
        if (warp_n == 1 && (lane & 3) == 0) {
            #pragma unroll
            for (int mt = 0; mt < 2; ++mt)
                #pragma unroll
                for (int hh = 0; hh < 2; ++hh) {
                    const int lr = warp_m * 32 + mt * 16 + hh * 8 + g;
                    Out[(size_t)blockIdx.y * MROWS + arow0 + lr] = ps[lr] + px[mt][hh];
                }
        }
    }
}

// =====================================================================
// head: xl = relu(part0 + part1 + blin); out = xl @ W_head^T + b_head
// =====================================================================
__global__ __launch_bounds__(256)
void head_k(const float* __restrict__ part, const float* __restrict__ blin,
            const float* __restrict__ Whead, const float* __restrict__ bhead,
            float* __restrict__ out) {
    __shared__ float xl_s[8][30];
    const int wid = threadIdx.x >> 5, lane = threadIdx.x & 31;
    const size_t b = (size_t)blockIdx.x * 8 + wid;
    if (lane < 30) {
        size_t r = b * 30 + lane;
        xl_s[wid][lane] = fmaxf(part[r] + part[MROWS + r] + blin[0], 0.f);
    }
    __syncwarp();
    if (lane < 9) {
        float s = bhead[lane];
        #pragma unroll
        for (int i = 0; i < 30; ++i) s = fmaf(xl_s[wid][i], Whead[lane * 30 + i], s);
        out[b * 9 + lane] = s;
    }
}

// =====================================================================
extern "C" void kernel_launch(void* const* d_in, const int* in_sizes, int n_in,
                              void* d_out, int out_size) {
    const float* real  = (const float*)d_in[0];
    const float* graph = (const float*)d_in[2];
    const float* W1    = (const float*)d_in[3];
    const float* b1    = (const float*)d_in[4];
    const float* W2    = (const float*)d_in[5];
    const float* b2    = (const float*)d_in[6];
    const float* wlin  = (const float*)d_in[7];
    const float* blin  = (const float*)d_in[8];
    const float* Whead = (const float*)d_in[9];
    const float* bhead = (const float*)d_in[10];
    float* out = (float*)d_out;

    float *adj_p, *h_p, *part_p;
    __nv_bfloat16 *ah_p, *al_p, *w1h_p, *w1l_p, *w2h_p, *w2l_p;
    cudaGetSymbolAddress((void**)&adj_p,  g_adj);
    cudaGetSymbolAddress((void**)&h_p,    g_h);
    cudaGetSymbolAddress((void**)&part_p, g_part);
    cudaGetSymbolAddress((void**)&ah_p,   g_ah);
    cudaGetSymbolAddress((void**)&al_p,   g_al);
    cudaGetSymbolAddress((void**)&w1h_p,  g_w1h);
    cudaGetSymbolAddress((void**)&w1l_p,  g_w1l);
    cudaGetSymbolAddress((void**)&w2h_p,  g_w2h);
    cudaGetSymbolAddress((void**)&w2l_p,  g_w2l);

    cudaFuncSetAttribute(gemm_hmma<1>, cudaFuncAttributeMaxDynamicSharedMemorySize, GEMM_SMEM);
    cudaFuncSetAttribute(gemm_hmma<2>, cudaFuncAttributeMaxDynamicSharedMemorySize, GEMM_SMEM);

    const dim3 ggrid(MROWS / 128, 2);

    // 1. weight transpose + bf16 split
    prep_w<<<256, 256>>>(W1, W2, w1h_p, w1l_p, w2h_p, w2l_p);
    // 2. adj = mean(graph); y1 = adj @ real (bf16 hi/lo)
    k_prep<<<BATCH, 128>>>(graph, real, adj_p, ah_p, al_p);
    // 3. h1 = relu(y1 @ W1 + b1)
    gemm_hmma<1><<<ggrid, 256, GEMM_SMEM>>>(ah_p, al_p, w1h_p, w1l_p, b1, nullptr, h_p);
    // 4. g2 = adj @ h1 (bf16 hi/lo)
    k_g2<<<BATCH, 128>>>(adj_p, h_p, ah_p, al_p);
    // 5. partial dots of relu(g2 @ W2 + b2) with wlin
    gemm_hmma<2><<<ggrid, 256, GEMM_SMEM>>>(ah_p, al_p, w2h_p, w2l_p, b2, wlin, part_p);
    // 6. xl = relu(p0+p1+blin); out = xl @ W_head^T + b_head
    head_k<<<BATCH / 8, 256>>>(part_p, blin, Whead, bhead, out);
}